// round 17
// baseline (speedup 1.0000x reference)
#include <cuda_runtime.h>
#include <cuda_fp16.h>
#include <cstdint>

// ---------------------------------------------------------------------------
// Fused GCN (BODY_25, fixed topology), R17: single-pass fp16 HMMA GEMM,
//   2 blocks/SM. G (128 x 132 fp32) OVERLAYS the A+B tile region; B is
//   reloaded from L2-hot global each tile (~272 wf). Phases serial within a
//   block (4 barriers); the co-resident sibling block hides the gaps.
// ---------------------------------------------------------------------------

#define NN      25
#define HID     128
#define SPB     5
#define THREADS 512
#define LDA     272          // A/B tile row stride in BYTES (136 fp16)
#define LDGf    132          // G row stride in floats

typedef unsigned long long u64;

// ---- compile-time normalized CSR (rows = dst), verified R6-R16 ----
__device__ constexpr float RSQ[6] = {0.f, 1.f, 0.70710678118654752f,
                                     0.57735026918962576f, 0.5f,
                                     0.44721359549995794f};
__device__ constexpr int RP[26]  = {0,3,8,10,12,13,15,17,18,21,23,25,28,30,32,
                                    35,37,39,40,41,43,44,45,47,48,49};
__device__ constexpr int COL[49] = {0,15,16, 1,0,2,5,8, 2,3, 3,4, 4, 5,6, 6,7, 7,
                                    8,9,12, 9,10, 10,11, 11,22,24, 12,13, 13,14,
                                    14,19,21, 15,17, 16,18, 17, 18, 19,20, 20, 21,
                                    22,23, 23, 24};
__device__ constexpr int DEGI[25] = {3,5,2,2,1,2,2,1,3,2,2,3,2,2,3,2,2,1,1,2,1,1,2,1,1};
__device__ constexpr int DEGO[25] = {2,1,2,2,2,2,2,2,2,2,2,2,2,2,2,2,2,2,2,2,2,2,2,2,2};
__device__ constexpr float EW(int n, int e) {
    return RSQ[DEGI[n]] * RSQ[DEGO[COL[e]]];
}

// ---- W2 as fp16 [k][n], padded LDA-byte rows ----
__device__ __align__(16) unsigned char g_w2[128 * LDA];   // 34816 B

__global__ void w2_split_kernel(const float* __restrict__ W2) {
    int i = blockIdx.x * blockDim.x + threadIdx.x;   // i = k*128 + n
    if (i < HID * HID) {
        int k = i >> 7, n = i & 127;
        *(__half*)(g_w2 + (uint32_t)k * LDA + (uint32_t)n * 2) =
            __float2half_rn(W2[i]);
    }
}

// ---- SMEM byte layout (tile region is OVERLAID) ----
// [0, 34816)      A (128 x 136 fp16)          |  G rows 0..
// [34816, 69632)  B (128 x 136 fp16)          |  ..G (G = 67584 B total)
// smalls (floats) at 69632
constexpr int A_OFF = 0, B_OFF = 34816, G_OFF = 0, SMALLB = 69632;
constexpr int FA1 = 0, FW1 = 768, FB1 = 1152, FB2 = 1280,
              FFC = 1408, FBF = 1664, FEND = 1668;
constexpr int SMEM_BYTES = SMALLB + FEND * 4;       // 76304 -> 2 blocks/SM

__device__ __forceinline__ uint32_t smem_u32(const void* p) {
    uint32_t a;
    asm("{ .reg .u64 t; cvta.to.shared.u64 t, %1; cvt.u32.u64 %0, t; }"
        : "=r"(a) : "l"(p));
    return a;
}

#define LDSM_X4(r0, r1, r2, r3, addr)                                          \
    asm volatile("ldmatrix.sync.aligned.m8n8.x4.shared.b16 {%0,%1,%2,%3}, [%4];" \
        : "=r"(r0), "=r"(r1), "=r"(r2), "=r"(r3) : "r"(addr))
#define LDSM_X4T(r0, r1, r2, r3, addr)                                         \
    asm volatile("ldmatrix.sync.aligned.m8n8.x4.trans.shared.b16 {%0,%1,%2,%3}, [%4];" \
        : "=r"(r0), "=r"(r1), "=r"(r2), "=r"(r3) : "r"(addr))
#define MMAF16(acc, a0, a1, a2, a3, bb0, bb1)                                  \
    asm volatile("mma.sync.aligned.m16n8k16.row.col.f32.f16.f16.f32 "          \
        "{%0,%1,%2,%3}, {%4,%5,%6,%7}, {%8,%9}, {%0,%1,%2,%3};"                \
        : "+f"((acc)[0]), "+f"((acc)[1]), "+f"((acc)[2]), "+f"((acc)[3])       \
        : "r"(a0), "r"(a1), "r"(a2), "r"(a3), "r"(bb0), "r"(bb1))

// AGG1 for one tile into sa1 (only threads tid < ns*3 <= 15 do work)
__device__ __forceinline__ void agg1(const float* __restrict__ x, int tile,
                                     int B, float* sa1, int tid) {
    const int ns = min(SPB, B - tile * SPB);
    if (tid < ns * 3) {
        int s = tid / 3, f = tid - 3 * s;
        const float* xs = x + (long long)(tile * SPB + s) * (NN * 3) + f;
        float xv[NN];
        #pragma unroll
        for (int n = 0; n < NN; n++) xv[n] = __ldg(xs + n * 3);
        #pragma unroll
        for (int n = 0; n < NN; n++) {
            float t = 0.f;
            #pragma unroll
            for (int e = RP[n]; e < RP[n + 1]; e++)
                t = fmaf(EW(n, e), xv[COL[e]], t);
            sa1[(s * NN + n) * 3 + f] = t;
        }
    }
}

// H1 rows [r0, r0+nr) -> A (fp16), lane owns 4 columns, conflict-free
__device__ __forceinline__ void phase1_rows(unsigned char* smb,
                                            const float* sW1, const float* sB1,
                                            const float* sa1, int r0, int nr,
                                            int nsn, int lane) {
    const float4 w0 = *(const float4*)(sW1 +       4 * lane);
    const float4 w1 = *(const float4*)(sW1 + 128 + 4 * lane);
    const float4 w2 = *(const float4*)(sW1 + 256 + 4 * lane);
    const float4 bb = *(const float4*)(sB1 +       4 * lane);
    unsigned char* baseA = smb + A_OFF + 8 * lane;
    for (int r = 0; r < nr; r++) {
        const int m  = r0 + r;
        const int mc = min(m, nsn - 1);
        const float a0 = sa1[mc * 3 + 0];
        const float a1 = sa1[mc * 3 + 1];
        const float a2 = sa1[mc * 3 + 2];
        float v0 = fmaxf(bb.x + a0 * w0.x + a1 * w1.x + a2 * w2.x, 0.f);
        float v1 = fmaxf(bb.y + a0 * w0.y + a1 * w1.y + a2 * w2.y, 0.f);
        float v2 = fmaxf(bb.z + a0 * w0.z + a1 * w1.z + a2 * w2.z, 0.f);
        float v3 = fmaxf(bb.w + a0 * w0.w + a1 * w1.w + a2 * w2.w, 0.f);
        __half2 p01 = __floats2half2_rn(v0, v1);
        __half2 p23 = __floats2half2_rn(v2, v3);
        *(uint2*)(baseA + m * LDA) =
            make_uint2(*(uint32_t*)&p01, *(uint32_t*)&p23);
    }
}

__global__ void __launch_bounds__(THREADS, 2)
gcn_hmma_persistent(const float* __restrict__ x,
                    const float* __restrict__ W1, const float* __restrict__ b1,
                    const float* __restrict__ b2,
                    const float* __restrict__ Wfc, const float* __restrict__ bfc,
                    float* __restrict__ out, int B)
{
    extern __shared__ __align__(16) unsigned char smb[];
    float* sG  = (float*)(smb + G_OFF);
    float* sSm = (float*)(smb + SMALLB);
    float* sA1 = sSm + FA1;          // 2 x 384
    float* sW1 = sSm + FW1;
    float* sB1 = sSm + FB1;
    float* sB2 = sSm + FB2;
    float* sFc = sSm + FFC;
    float* sBf = sSm + FBF;

    const uint32_t sb = smem_u32(smb);
    const int tid = threadIdx.x;
    const int wid = tid >> 5, lane = tid & 31;
    const int ntiles = (B + SPB - 1) / SPB;

    // ---- one-time staging ---------------------------------------------------
    if (tid < 384) sW1[tid] = W1[tid];
    if (tid < 128) { sB1[tid] = b1[tid]; sB2[tid] = b2[tid]; }
    if (tid < 256) sFc[tid] = Wfc[tid];
    if (tid < 2)   sBf[tid] = bfc[tid];

    int t = blockIdx.x;
    if (t >= ntiles) return;

    // prologue: B load + AGG1(t), then phase1(t)
    {
        const uint4* src = (const uint4*)g_w2;
        uint4* dst = (uint4*)(smb + B_OFF);
        #pragma unroll
        for (int i = tid; i < 2176; i += THREADS) dst[i] = src[i];
    }
    agg1(x, t, B, sA1, tid);
    __syncthreads();
    {
        const int nsn = min(SPB, B - t * SPB) * NN;
        phase1_rows(smb, sW1, sB1, sA1, wid * 8, 8, nsn, lane);
    }
    __syncthreads();                   // A, B ready

    const int mt = wid & 3, nh = wid >> 2;      // 4 m-tiles x 4 n-quarters
    const int m0 = mt << 5;
    int buf = 0;

    for (; t < ntiles; t += gridDim.x) {
        const int ns = min(SPB, B - t * SPB);
        const int tn = t + gridDim.x;

        // ---- R1: AGG1(t+1) [<=15 threads] + GEMM(t) -------------------------
        if (tn < ntiles) agg1(x, tn, B, sA1 + 384 * (buf ^ 1), tid);

        float acc[2][4][4];
        #pragma unroll
        for (int i = 0; i < 2; i++)
            #pragma unroll
            for (int j = 0; j < 4; j++)
                #pragma unroll
                for (int q = 0; q < 4; q++) acc[i][j][q] = 0.f;

        {
            const uint32_t aBase = sb + A_OFF
                + (uint32_t)(m0 + (lane & 15)) * LDA + ((lane >> 4) << 4);
            const uint32_t bBase = sb + B_OFF
                + (uint32_t)(lane & 15) * LDA + ((lane >> 4) << 4) + (nh << 6);

            #pragma unroll 1
            for (int kk = 0; kk < 8; kk++) {
                const uint32_t ka = kk * 32;
                const uint32_t kb = kk * (16 * LDA);
                uint32_t ah0[4], ah1[4];
                LDSM_X4(ah0[0], ah0[1], ah0[2], ah0[3], aBase + ka);
                LDSM_X4(ah1[0], ah1[1], ah1[2], ah1[3], aBase + ka + 16 * LDA);
                #pragma unroll
                for (int c = 0; c < 2; c++) {           // n16 chunks in quarter
                    uint32_t bh[4];
                    LDSM_X4T(bh[0], bh[1], bh[2], bh[3], bBase + kb + c * 32);
                    const int na = c << 1;
                    MMAF16(acc[0][na  ], ah0[0], ah0[1], ah0[2], ah0[3], bh[0], bh[1]);
                    MMAF16(acc[0][na+1], ah0[0], ah0[1], ah0[2], ah0[3], bh[2], bh[3]);
                    MMAF16(acc[1][na  ], ah1[0], ah1[1], ah1[2], ah1[3], bh[0], bh[1]);
                    MMAF16(acc[1][na+1], ah1[0], ah1[1], ah1[2], ah1[3], bh[2], bh[3]);
                }
            }
        }
        __syncthreads();               // all warps done reading A, B

        // ---- R2: G store (overlays A+B region) ------------------------------
        {
            const int g  = lane >> 2;
            const int t2 = (lane & 3) << 1;
            const int c0 = (nh << 5) + t2;
            #pragma unroll
            for (int ma = 0; ma < 2; ma++) {
                const int r0 = m0 + (ma << 4) + g;
                #pragma unroll
                for (int na = 0; na < 4; na++) {
                    const int col = c0 + (na << 3);
                    *(float2*)(sG + r0 * LDGf + col) =
                        make_float2(acc[ma][na][0], acc[ma][na][1]);
                    *(float2*)(sG + (r0 + 8) * LDGf + col) =
                        make_float2(acc[ma][na][2], acc[ma][na][3]);
                }
            }
        }
        __syncthreads();               // G complete

        // ---- R3: pool+FC(t), one warp per sample -----------------------------
        if (wid < ns) {
            const float4* G4 = (const float4*)sG;
            const int base = wid * NN;
            const float4 bb = ((const float4*)sB2)[lane];
            float4 pooled = make_float4(0.f, 0.f, 0.f, 0.f);
            #pragma unroll
            for (int n = 0; n < NN; n++) {
                float4 tt = make_float4(0.f, 0.f, 0.f, 0.f);
                #pragma unroll
                for (int e = RP[n]; e < RP[n + 1]; e++) {
                    const float w = EW(n, e);
                    float4 g = G4[(base + COL[e]) * (LDGf / 4) + lane];
                    tt.x = fmaf(w, g.x, tt.x);
                    tt.y = fmaf(w, g.y, tt.y);
                    tt.z = fmaf(w, g.z, tt.z);
                    tt.w = fmaf(w, g.w, tt.w);
                }
                pooled.x += fmaxf(tt.x + bb.x, 0.f);
                pooled.y += fmaxf(tt.y + bb.y, 0.f);
                pooled.z += fmaxf(tt.z + bb.z, 0.f);
                pooled.w += fmaxf(tt.w + bb.w, 0.f);
            }
            const float4 f01 = ((const float4*)sFc)[2 * lane];
            const float4 f23 = ((const float4*)sFc)[2 * lane + 1];
            float p0 = 0.04f * (pooled.x * f01.x + pooled.y * f01.z
                              + pooled.z * f23.x + pooled.w * f23.z);
            float p1 = 0.04f * (pooled.x * f01.y + pooled.y * f01.w
                              + pooled.z * f23.y + pooled.w * f23.w);
            #pragma unroll
            for (int o = 16; o; o >>= 1) {
                p0 += __shfl_xor_sync(0xffffffff, p0, o);
                p1 += __shfl_xor_sync(0xffffffff, p1, o);
            }
            if (lane == 0) {
                int b = t * SPB + wid;
                out[b * 2 + 0] = p0 + sBf[0];
                out[b * 2 + 1] = p1 + sBf[1];
            }
        }
        __syncthreads();               // pool done reading G

        // ---- R4: B reload + phase1(t+1) rebuild A (all warps) ----------------
        if (tn < ntiles) {
            {
                const uint4* src = (const uint4*)g_w2;
                uint4* dst = (uint4*)(smb + B_OFF);
                #pragma unroll
                for (int i = tid; i < 2176; i += THREADS) dst[i] = src[i];
            }
            const int nsn2 = min(SPB, B - tn * SPB) * NN;
            phase1_rows(smb, sW1, sB1, sA1 + 384 * (buf ^ 1),
                        wid * 8, 8, nsn2, lane);
        }
        __syncthreads();               // A, B ready for next iter
        buf ^= 1;
    }
}

extern "C" void kernel_launch(void* const* d_in, const int* in_sizes, int n_in,
                              void* d_out, int out_size)
{
    const float *x = 0, *W1 = 0, *b1 = 0, *W2 = 0, *b2 = 0, *Wfc = 0, *bfc = 0;
    int B = 0;
    for (int i = 0; i < n_in; i++) {
        int s = in_sizes[i];
        if      (s == 16384) W2  = (const float*)d_in[i];
        else if (s == 384)   W1  = (const float*)d_in[i];
        else if (s == 256)   Wfc = (const float*)d_in[i];
        else if (s == 2)     bfc = (const float*)d_in[i];
        else if (s == 128)   { if (!b1) b1 = (const float*)d_in[i];
                               else     b2 = (const float*)d_in[i]; }
        else if (s > 16384)  { x = (const float*)d_in[i]; B = s / (NN * 3); }
    }
    float* out = (float*)d_out;

    w2_split_kernel<<<32, 512>>>(W2);

    int sms = 148;
    cudaDeviceGetAttribute(&sms, cudaDevAttrMultiProcessorCount, 0);
    const int ntiles = (B + SPB - 1) / SPB;
    const int maxb = 2 * sms;
    const int grid = (ntiles < maxb) ? ntiles : maxb;

    cudaFuncSetAttribute(gcn_hmma_persistent,
                         cudaFuncAttributeMaxDynamicSharedMemorySize, SMEM_BYTES);
    gcn_hmma_persistent<<<grid, THREADS, SMEM_BYTES>>>(x, W1, b1, b2, Wfc, bfc,
                                                       out, B);
}